// round 3
// baseline (speedup 1.0000x reference)
#include <cuda_runtime.h>
#include <cstddef>

#define B_SZ 1024
#define NF   800
#define L1D  1024

// Scratch (no allocation allowed — __device__ globals)
__device__ float g_vals[B_SZ * NF];   // gated conv features, (B, 800) row-major
__device__ float g_l0[B_SZ * L1D];    // clipped features,    (B, 1024) row-major

// ---------------------------------------------------------------------------
// Kernel 1: strided conv (3x3, stride 10, pad 1) + clip + sigmoid gate.
// One thread per (batch, output position); 8 output channels in registers.
// ---------------------------------------------------------------------------
__global__ __launch_bounds__(128) void conv_act_kernel(
    const float* __restrict__ images, const float* __restrict__ conv_w) {
    __shared__ float w[216];  // (8,3,3,3)
    int t = threadIdx.x;
    // FIX: blockDim=128 < 216 — must stride so w[128..215] gets initialized.
    for (int i = t; i < 216; i += 128) w[i] = conv_w[i];
    __syncthreads();

    int gid = blockIdx.x * 128 + t;
    if (gid >= B_SZ * 100) return;
    int b  = gid / 100;
    int p  = gid - b * 100;      // oy*10 + ox
    int oy = p / 10;
    int ox = p - oy * 10;

    const float* img = images + (size_t)b * 3 * 96 * 96;
    float acc[8];
#pragma unroll
    for (int c = 0; c < 8; c++) acc[c] = 0.f;

    int iy0 = oy * 10 - 1;
    int ix0 = ox * 10 - 1;
#pragma unroll
    for (int ic = 0; ic < 3; ic++) {
#pragma unroll
        for (int ky = 0; ky < 3; ky++) {
            int iy = iy0 + ky;
            if (iy < 0) continue;   // only oy==0,ky==0 pads; upper bound never hit
#pragma unroll
            for (int kx = 0; kx < 3; kx++) {
                int ix = ix0 + kx;
                if (ix < 0) continue;
                float v = __ldg(img + ic * 9216 + iy * 96 + ix);
#pragma unroll
                for (int c = 0; c < 8; c++)
                    acc[c] = fmaf(v, w[c * 27 + ic * 9 + ky * 3 + kx], acc[c]);
            }
        }
    }

#pragma unroll
    for (int c = 0; c < 8; c++) {
        float x = fminf(fmaxf(acc[c], -1.f), 1.f);        // clip(-1, 1)
        float s = 1.f / (1.f + __expf(-10.f * x));        // sigmoid(10*x)
        g_vals[(size_t)b * NF + c * 100 + p] = (s > 0.5f) ? s : 0.f;
    }
}

// ---------------------------------------------------------------------------
// Kernel 2: features = vals(1024x800) @ ft_w(800x1024) + ft_b, clip to [0,1].
// 128x64 tile, BK=16, 256 threads, 8x4 register tile. A staged transposed.
// ---------------------------------------------------------------------------
#define BM 128
#define BN 64
#define BK 16

__global__ __launch_bounds__(256) void feat_gemm_kernel(
    const float* __restrict__ Bw, const float* __restrict__ bias) {
    __shared__ float As[BK][BM + 4];   // transposed A tile, padded
    __shared__ float Bs[BK][BN];

    int t  = threadIdx.x;
    int bm = blockIdx.y * BM;
    int bn = blockIdx.x * BN;
    int tx = t & 15;
    int ty = t >> 4;

    float acc[8][4];
#pragma unroll
    for (int i = 0; i < 8; i++)
#pragma unroll
        for (int j = 0; j < 4; j++) acc[i][j] = 0.f;

    for (int k0 = 0; k0 < NF; k0 += BK) {
        // A tile: 128x16 = 512 float4, 2 per thread, stored transposed
#pragma unroll
        for (int v = 0; v < 2; v++) {
            int lin = t + v * 256;
            int row = lin >> 2;
            int q   = (lin & 3) << 2;
            const float4 a4 = *(const float4*)(g_vals + (size_t)(bm + row) * NF + k0 + q);
            As[q + 0][row] = a4.x;
            As[q + 1][row] = a4.y;
            As[q + 2][row] = a4.z;
            As[q + 3][row] = a4.w;
        }
        // B tile: 16x64 = 256 float4, 1 per thread
        {
            int r = t >> 4;
            int c = (t & 15) << 2;
            *(float4*)(&Bs[r][c]) =
                *(const float4*)(Bw + (size_t)(k0 + r) * L1D + bn + c);
        }
        __syncthreads();

#pragma unroll
        for (int kk = 0; kk < BK; kk++) {
            float4 b4 = *(const float4*)(&Bs[kk][tx << 2]);
            float4 a0 = *(const float4*)(&As[kk][ty << 3]);
            float4 a1 = *(const float4*)(&As[kk][(ty << 3) + 4]);
            float a[8] = {a0.x, a0.y, a0.z, a0.w, a1.x, a1.y, a1.z, a1.w};
            float bb[4] = {b4.x, b4.y, b4.z, b4.w};
#pragma unroll
            for (int i = 0; i < 8; i++)
#pragma unroll
                for (int j = 0; j < 4; j++)
                    acc[i][j] = fmaf(a[i], bb[j], acc[i][j]);
        }
        __syncthreads();
    }

    float4 bias4 = *(const float4*)(bias + bn + (tx << 2));
    float bv[4] = {bias4.x, bias4.y, bias4.z, bias4.w};
#pragma unroll
    for (int i = 0; i < 8; i++) {
        int row = bm + (ty << 3) + i;
        float4 o;
        o.x = fminf(fmaxf(acc[i][0] + bv[0], 0.f), 1.f);
        o.y = fminf(fmaxf(acc[i][1] + bv[1], 0.f), 1.f);
        o.z = fminf(fmaxf(acc[i][2] + bv[2], 0.f), 1.f);
        o.w = fminf(fmaxf(acc[i][3] + bv[3], 0.f), 1.f);
        *(float4*)(g_l0 + (size_t)row * L1D + bn + (tx << 2)) = o;
    }
}

// ---------------------------------------------------------------------------
// Kernel 3: tail MLP, one warp per sample.
// l0c[j<512]  = l0[j]*l0[j+512]*(127/128)
// l0c[j>=512] = l0[j-512]*(127/128)
// h1 = relu(l0c @ w1^T + b1)  (15); h2 = relu(h1 @ w2^T + b2) (32); out = h2 @ w3^T + b3.
// Lane L owns j in [L*32, L*32+32): lanes<16 cover first half, lanes>=16 second.
// Cross-half pairing via shfl_xor(16).
// ---------------------------------------------------------------------------
__global__ __launch_bounds__(256) void tail_kernel(
    const float* __restrict__ w1, const float* __restrict__ b1,
    const float* __restrict__ w2, const float* __restrict__ b2,
    const float* __restrict__ w3, const float* __restrict__ b3,
    float* __restrict__ out) {
    int warp = (blockIdx.x * 256 + threadIdx.x) >> 5;
    int lane = threadIdx.x & 31;
    if (warp >= B_SZ) return;

    const float* x = g_l0 + (size_t)warp * L1D + lane * 32;
    const float KC = 127.f / 128.f;

    float c4[8][4];
#pragma unroll
    for (int g = 0; g < 8; g++) {
        float4 r = *(const float4*)(x + g * 4);
        float rr[4] = {r.x, r.y, r.z, r.w};
#pragma unroll
        for (int e = 0; e < 4; e++) {
            float other = __shfl_xor_sync(0xffffffffu, rr[e], 16);
            // lanes < 16: s0*s1*K ;  lanes >= 16: s0*K (s0 lives in lane-16)
            c4[g][e] = (lane < 16) ? (rr[e] * other * KC) : (other * KC);
        }
    }

    float h1[15];
#pragma unroll
    for (int o = 0; o < 15; o++) {
        const float* wr = w1 + (size_t)o * L1D + lane * 32;
        float a = 0.f;
#pragma unroll
        for (int g = 0; g < 8; g++) {
            float4 wv = *(const float4*)(wr + g * 4);
            a = fmaf(c4[g][0], wv.x, a);
            a = fmaf(c4[g][1], wv.y, a);
            a = fmaf(c4[g][2], wv.z, a);
            a = fmaf(c4[g][3], wv.w, a);
        }
#pragma unroll
        for (int s = 16; s; s >>= 1) a += __shfl_xor_sync(0xffffffffu, a, s);
        h1[o] = fmaxf(a + __ldg(b1 + o), 0.f);
    }

    // h2: one of 32 outputs per lane
    float h2 = __ldg(b2 + lane);
#pragma unroll
    for (int k = 0; k < 15; k++)
        h2 = fmaf(h1[k], __ldg(w2 + lane * 15 + k), h2);
    h2 = fmaxf(h2, 0.f);

    float ov = h2 * __ldg(w3 + lane);
#pragma unroll
    for (int s = 16; s; s >>= 1) ov += __shfl_xor_sync(0xffffffffu, ov, s);
    if (lane == 0) out[warp] = ov + __ldg(b3);
}

// ---------------------------------------------------------------------------
// Identify inputs by element count (robust to metadata ordering).
// Sizes: images 28311552, conv_w 216, ft_w 819200, ft_b 1024, w1 15360,
//        b1 15, w2 480, b2 32, w3 32, b3 1.
// Only b2/w3 collide at 32; in both insertion and alphabetical orderings
// b2 precedes w3, so: first 32-elem input = b2, second = w3.
// ---------------------------------------------------------------------------
extern "C" void kernel_launch(void* const* d_in, const int* in_sizes, int n_in,
                              void* d_out, int out_size) {
    const float *images = 0, *conv_w = 0, *ft_w = 0, *ft_b = 0;
    const float *w1 = 0, *b1 = 0, *w2 = 0, *b2 = 0, *w3 = 0, *b3 = 0;

    for (int i = 0; i < n_in; i++) {
        const float* p = (const float*)d_in[i];
        switch (in_sizes[i]) {
            case 28311552: images = p; break;
            case 216:      conv_w = p; break;
            case 819200:   ft_w   = p; break;
            case 1024:     ft_b   = p; break;
            case 15360:    w1     = p; break;
            case 15:       b1     = p; break;
            case 480:      w2     = p; break;
            case 32:       if (!b2) b2 = p; else w3 = p; break;
            case 1:        b3     = p; break;
            default: break;
        }
    }
    float* out = (float*)d_out;

    conv_act_kernel<<<(B_SZ * 100 + 127) / 128, 128>>>(images, conv_w);

    dim3 g2(L1D / BN, B_SZ / BM);  // 16 x 8 = 128 blocks
    feat_gemm_kernel<<<g2, 256>>>(ft_w, ft_b);

    tail_kernel<<<B_SZ / 8, 256>>>(w1, b1, w2, b2, w3, b3, out);
}